// round 13
// baseline (speedup 1.0000x reference)
#include <cuda_runtime.h>
#include <cuda_bf16.h>

#define NUM_CLASSES 10

// Barrier-free variant in the empirically-fast 192-thread launch shape.
// Warp 0 does all the work: lanes 0..23 each own (channel, row) of the
// 3x8x8 top-left patch and load the 8-float row as two float4 (LDG.128 x2,
// 16B-aligned). Butterfly shuffles give every lane the total; lanes 0..9
// write the logits as one coalesced 40B burst. Warps 1..5 exit
// immediately. No shared memory, no __syncthreads.
__global__ __launch_bounds__(192, 8)
void ldc_kernel(const float* __restrict__ x, float* __restrict__ out) {
    const unsigned tid = threadIdx.x;
    if (tid >= 32u) return;              // warps 1..5 retire immediately

    const unsigned b    = blockIdx.x;    // batch 0..63
    const unsigned lane = tid;           // 0..31

    float v = 0.0f;
    if (lane < 24u) {
        const unsigned c = lane >> 3;    // channel 0..2
        const unsigned r = lane & 7u;    // row 0..7
        // 32-bit offset: ((b*3 + c) << 18) + (r << 9); max < 2^31.
        const unsigned idx = ((b * 3u + c) << 18) + (r << 9);
        const float4* p = (const float4*)(x + idx);
        float4 a0 = p[0];
        float4 a1 = p[1];
        v = ((a0.x + a0.y) + (a0.z + a0.w)) + ((a1.x + a1.y) + (a1.z + a1.w));
    }

    // Butterfly reduce: all lanes end with the full sum over 192 elements.
    #pragma unroll
    for (int off = 16; off > 0; off >>= 1)
        v += __shfl_xor_sync(0xFFFFFFFFu, v, off);

    const float mean = v / 192.0f;
    // Python int() truncates toward zero; % with positive modulus is
    // non-negative.
    int t = (int)truncf(mean * 10.0f);
    int pred = t % NUM_CLASSES;
    if (pred < 0) pred += NUM_CLASSES;

    if (lane < NUM_CLASSES)
        out[b * NUM_CLASSES + lane] = ((int)lane == pred) ? 10.0f : 0.0f;
}

extern "C" void kernel_launch(void* const* d_in, const int* in_sizes, int n_in,
                              void* d_out, int out_size) {
    const float* x = (const float*)d_in[0];
    float* out = (float*)d_out;
    ldc_kernel<<<64, 192>>>(x, out);
}